// round 3
// baseline (speedup 1.0000x reference)
#include <cuda_runtime.h>
#include <math.h>

// Problem constants
#define NB 128          // batch
#define NN 32           // spans
#define NLW 36          // image regions L
#define DS 512
#define DV 1024
#define HH 512
#define NP 496          // N*(N-1)/2 pairs
#define NNL (NN*NLW)    // 1152
#define BNROWS (NB*NN)  // 4096
#define BPROWS (NB*NP)  // 63488

// ---- scratch (static device globals; no runtime allocation) ----
__device__ float g_G[(size_t)BNROWS * DV];     // S@Wg        16.8 MB
__device__ float g_U[(size_t)BNROWS * HH];     // S@W1a        8.4 MB
__device__ float g_V[(size_t)BNROWS * HH];     // S@W1b        8.4 MB
__device__ float g_M[NB * NNL];                // M            0.6 MB
__device__ float g_Avec[NB * NLW];
__device__ float g_cs[NB];
__device__ float g_ci[NB];
__device__ float g_Msum[NB];
__device__ float g_sent[NB * NB];
__device__ float g_H1[(size_t)BPROWS * HH];    // 130 MB
__device__ float g_H2[(size_t)BPROWS * HH];    // 130 MB
__device__ int   g_iu[NP];
__device__ int   g_ju[NP];

// ---------------------------------------------------------------
// init pair indices (triu_indices(N, k=1), row-major order)
__global__ void k_init_pairs() {
    int p = threadIdx.x;
    if (p >= NP) return;
    int cum = 0;
    for (int i = 0; i < NN; i++) {
        int cnt = NN - 1 - i;
        if (p < cum + cnt) { g_iu[p] = i; g_ju[p] = i + 1 + (p - cum); return; }
        cum += cnt;
    }
}

// ---------------------------------------------------------------
// Generic fp32 SGEMM core: C[M x Nd] = op(A[M x Kd] @ B[Kd x Nd] (+bias) (relu))
// BM=BN=128, BK=16, 256 threads, 8x8 per thread. All dims divide evenly.
template<bool RELU, bool BIAS>
__device__ __forceinline__ void gemm_core(
    const float* __restrict__ A, const float* __restrict__ Bm,
    const float* __restrict__ bias, float* __restrict__ C,
    int Ndim, int Kdim)
{
    __shared__ float As[16][128];
    __shared__ float Bs[16][128];
    const int tid = threadIdx.x;
    const int m0 = blockIdx.y * 128;
    const int n0 = blockIdx.x * 128;

    // A loads: 512 float4 per tile; thread handles q=tid and q=tid+256
    const int ar0 = tid >> 2, ac0 = (tid & 3) << 2;
    const int ar1 = ar0 + 64, ac1 = ac0;
    const float* Ap0 = A + (size_t)(m0 + ar0) * Kdim + ac0;
    const float* Ap1 = A + (size_t)(m0 + ar1) * Kdim + ac1;
    // B loads: rows tid>>5 and tid>>5 + 8
    const int brow = tid >> 5, bcol = (tid & 31) << 2;
    const float* Bp0 = Bm + (size_t)brow * Ndim + n0 + bcol;
    const float* Bp1 = Bm + (size_t)(brow + 8) * Ndim + n0 + bcol;

    const int tm = (tid >> 4) << 3;
    const int tn = (tid & 15) << 3;
    float acc[8][8];
    #pragma unroll
    for (int i = 0; i < 8; i++)
        #pragma unroll
        for (int j = 0; j < 8; j++) acc[i][j] = 0.f;

    for (int kt = 0; kt < Kdim; kt += 16) {
        float4 a0 = *(const float4*)(Ap0 + kt);
        float4 a1 = *(const float4*)(Ap1 + kt);
        float4 b0 = *(const float4*)(Bp0 + (size_t)kt * Ndim);
        float4 b1 = *(const float4*)(Bp1 + (size_t)kt * Ndim);
        __syncthreads();
        As[ac0 + 0][ar0] = a0.x; As[ac0 + 1][ar0] = a0.y;
        As[ac0 + 2][ar0] = a0.z; As[ac0 + 3][ar0] = a0.w;
        As[ac1 + 0][ar1] = a1.x; As[ac1 + 1][ar1] = a1.y;
        As[ac1 + 2][ar1] = a1.z; As[ac1 + 3][ar1] = a1.w;
        *(float4*)&Bs[brow][bcol]     = b0;
        *(float4*)&Bs[brow + 8][bcol] = b1;
        __syncthreads();
        #pragma unroll
        for (int kk = 0; kk < 16; kk++) {
            float a[8], b[8];
            *(float4*)&a[0] = *(const float4*)&As[kk][tm];
            *(float4*)&a[4] = *(const float4*)&As[kk][tm + 4];
            *(float4*)&b[0] = *(const float4*)&Bs[kk][tn];
            *(float4*)&b[4] = *(const float4*)&Bs[kk][tn + 4];
            #pragma unroll
            for (int i = 0; i < 8; i++)
                #pragma unroll
                for (int j = 0; j < 8; j++)
                    acc[i][j] = fmaf(a[i], b[j], acc[i][j]);
        }
    }
    #pragma unroll
    for (int i = 0; i < 8; i++) {
        float* Cr = C + (size_t)(m0 + tm + i) * Ndim + n0 + tn;
        #pragma unroll
        for (int j = 0; j < 8; j++) {
            float v = acc[i][j];
            if (BIAS) v += bias[n0 + tn + j];
            if (RELU) v = fmaxf(v, 0.f);
            Cr[j] = v;
        }
    }
}

__global__ __launch_bounds__(256) void k_gemm_G(const float* __restrict__ S,
                                                const float* __restrict__ Wg) {
    gemm_core<false, false>(S, Wg, nullptr, g_G, DV, DS);
}
__global__ __launch_bounds__(256) void k_gemm_U(const float* __restrict__ S,
                                                const float* __restrict__ W1a) {
    gemm_core<false, false>(S, W1a, nullptr, g_U, HH, DS);
}
__global__ __launch_bounds__(256) void k_gemm_V(const float* __restrict__ S,
                                                const float* __restrict__ W1b) {
    gemm_core<false, false>(S, W1b, nullptr, g_V, HH, DS);
}
__global__ __launch_bounds__(256) void k_gemm_H2(const float* __restrict__ W2,
                                                 const float* __restrict__ b2) {
    gemm_core<true, true>(g_H1, W2, b2, g_H2, HH, HH);
}

// ---------------------------------------------------------------
// Product-GEMM: H1 = relu( (S[iu]⊙S[ju]) @ W1c + U[iu] + V[ju] + b1 )
__global__ __launch_bounds__(256) void k_prodgemm(
    const float* __restrict__ S, const float* __restrict__ W1c,
    const float* __restrict__ b1)
{
    __shared__ float As[16][128];
    __shared__ float Bs[16][128];
    const int Ndim = HH, Kdim = DS;
    const int tid = threadIdx.x;
    const int m0 = blockIdx.y * 128;
    const int n0 = blockIdx.x * 128;

    const int ar0 = tid >> 2, ac0 = (tid & 3) << 2;
    const int ar1 = ar0 + 64, ac1 = ac0;
    const int m_0 = m0 + ar0, m_1 = m0 + ar1;
    const int bI0 = m_0 / NP, p0 = m_0 - bI0 * NP;
    const int bI1 = m_1 / NP, p1 = m_1 - bI1 * NP;
    const float* SU0 = S + (size_t)(bI0 * NN + g_iu[p0]) * DS + ac0;
    const float* SV0 = S + (size_t)(bI0 * NN + g_ju[p0]) * DS + ac0;
    const float* SU1 = S + (size_t)(bI1 * NN + g_iu[p1]) * DS + ac1;
    const float* SV1 = S + (size_t)(bI1 * NN + g_ju[p1]) * DS + ac1;

    const int brow = tid >> 5, bcol = (tid & 31) << 2;
    const float* Bp0 = W1c + (size_t)brow * Ndim + n0 + bcol;
    const float* Bp1 = W1c + (size_t)(brow + 8) * Ndim + n0 + bcol;

    const int tm = (tid >> 4) << 3;
    const int tn = (tid & 15) << 3;
    float acc[8][8];
    #pragma unroll
    for (int i = 0; i < 8; i++)
        #pragma unroll
        for (int j = 0; j < 8; j++) acc[i][j] = 0.f;

    for (int kt = 0; kt < Kdim; kt += 16) {
        float4 u0 = *(const float4*)(SU0 + kt);
        float4 v0 = *(const float4*)(SV0 + kt);
        float4 u1 = *(const float4*)(SU1 + kt);
        float4 v1 = *(const float4*)(SV1 + kt);
        float4 bb0 = *(const float4*)(Bp0 + (size_t)kt * Ndim);
        float4 bb1 = *(const float4*)(Bp1 + (size_t)kt * Ndim);
        __syncthreads();
        As[ac0 + 0][ar0] = u0.x * v0.x; As[ac0 + 1][ar0] = u0.y * v0.y;
        As[ac0 + 2][ar0] = u0.z * v0.z; As[ac0 + 3][ar0] = u0.w * v0.w;
        As[ac1 + 0][ar1] = u1.x * v1.x; As[ac1 + 1][ar1] = u1.y * v1.y;
        As[ac1 + 2][ar1] = u1.z * v1.z; As[ac1 + 3][ar1] = u1.w * v1.w;
        *(float4*)&Bs[brow][bcol]     = bb0;
        *(float4*)&Bs[brow + 8][bcol] = bb1;
        __syncthreads();
        #pragma unroll
        for (int kk = 0; kk < 16; kk++) {
            float a[8], b[8];
            *(float4*)&a[0] = *(const float4*)&As[kk][tm];
            *(float4*)&a[4] = *(const float4*)&As[kk][tm + 4];
            *(float4*)&b[0] = *(const float4*)&Bs[kk][tn];
            *(float4*)&b[4] = *(const float4*)&Bs[kk][tn + 4];
            #pragma unroll
            for (int i = 0; i < 8; i++)
                #pragma unroll
                for (int j = 0; j < 8; j++)
                    acc[i][j] = fmaf(a[i], b[j], acc[i][j]);
        }
    }
    #pragma unroll
    for (int i = 0; i < 8; i++) {
        const int m = m0 + tm + i;
        const int bb = m / NP, pp = m - bb * NP;
        const float* Ur = g_U + (size_t)(bb * NN + g_iu[pp]) * HH + n0 + tn;
        const float* Vr = g_V + (size_t)(bb * NN + g_ju[pp]) * HH + n0 + tn;
        float* Cr = g_H1 + (size_t)m * HH + n0 + tn;
        #pragma unroll
        for (int j = 0; j < 8; j++) {
            float v = acc[i][j] + Ur[j] + Vr[j] + b1[n0 + tn + j];
            Cr[j] = fmaxf(v, 0.f);
        }
    }
}

// ---------------------------------------------------------------
// M[b,n,l] = sum_e G[b,n,e] * I[b,l,e]; write to scratch and to out (+1 offset)
__global__ __launch_bounds__(256) void k_M(const float* __restrict__ I,
                                           float* __restrict__ out)
{
    __shared__ float Gs[32][65];
    __shared__ float Is[40][65];
    const int b = blockIdx.x;
    const int tid = threadIdx.x;
    const int n = tid >> 3;      // 0..31
    const int lg = tid & 7;      // 0..7
    float acc[5] = {0.f, 0.f, 0.f, 0.f, 0.f};

    for (int kt = 0; kt < DV; kt += 64) {
        __syncthreads();
        for (int t = tid; t < 32 * 64; t += 256) {
            int r = t >> 6, c = t & 63;
            Gs[r][c] = g_G[(size_t)(b * NN + r) * DV + kt + c];
        }
        for (int t = tid; t < 40 * 64; t += 256) {
            int r = t >> 6, c = t & 63;
            Is[r][c] = (r < NLW) ? I[(size_t)b * NLW * DV + (size_t)r * DV + kt + c] : 0.f;
        }
        __syncthreads();
        #pragma unroll 4
        for (int c = 0; c < 64; c++) {
            float g = Gs[n][c];
            #pragma unroll
            for (int s = 0; s < 5; s++)
                acc[s] = fmaf(g, Is[lg + 8 * s][c], acc[s]);
        }
    }
    #pragma unroll
    for (int s = 0; s < 5; s++) {
        int l = lg + 8 * s;
        if (l < NLW) {
            float v = acc[s];
            g_M[b * NNL + n * NLW + l] = v;
            out[1 + b * NNL + n * NLW + l] = v;
        }
    }
}

// ---------------------------------------------------------------
// A[b,l] = sum_n M[b,n,l]*sm[b,n]; also cs, ci, Msum. 64 threads/block.
__global__ void k_A(const float* __restrict__ sm, const float* __restrict__ im)
{
    const int b = blockIdx.x, t = threadIdx.x;
    __shared__ float red[64];
    __shared__ float sms[32];
    if (t < 32) sms[t] = sm[b * NN + t];
    __syncthreads();
    float msum = 0.f;
    for (int o = t; o < NNL; o += 64) msum += g_M[b * NNL + o];
    red[t] = msum;
    if (t < NLW) {
        float a = 0.f;
        #pragma unroll
        for (int n = 0; n < NN; n++)
            a = fmaf(g_M[b * NNL + n * NLW + t], sms[n], a);
        g_Avec[b * NLW + t] = a;
    }
    __syncthreads();
    for (int s = 32; s > 0; s >>= 1) {
        if (t < s) red[t] += red[t + s];
        __syncthreads();
    }
    if (t == 0) {
        g_Msum[b] = red[0];
        float cs = 0.f, ci = 0.f;
        for (int n = 0; n < NN; n++) cs += sms[n];
        for (int l = 0; l < NLW; l++) ci += im[b * NLW + l];
        g_cs[b] = cs;
        g_ci[b] = ci;
    }
}

// sent[i,j]
__global__ void k_sent(const float* __restrict__ im)
{
    const int i = blockIdx.x, j = threadIdx.x;   // 128 threads
    __shared__ float As[NLW];
    __shared__ float csI, msI;
    if (j < NLW) As[j] = g_Avec[i * NLW + j];
    if (j == 0) { csI = g_cs[i]; msI = g_Msum[i]; }
    __syncthreads();
    float d = 0.f;
    #pragma unroll
    for (int l = 0; l < NLW; l++) d = fmaf(As[l], im[j * NLW + l], d);
    float cnt = csI * g_ci[j];
    g_sent[i * NB + j] = (cnt > 0.f) ? (d / cnt) : (msI / (float)NNL);
}

// loss = sum_i lse_row[i] + sum_j lse_col[j] - 2*sum(sent)/B
__global__ void k_loss(float* __restrict__ out)
{
    const int t = threadIdx.x;   // 128
    float mx = -1e30f;
    for (int j = 0; j < NB; j++) mx = fmaxf(mx, g_sent[t * NB + j]);
    float se = 0.f, rs = 0.f;
    for (int j = 0; j < NB; j++) {
        float v = g_sent[t * NB + j];
        se += expf(v - mx);
        rs += v;
    }
    float lr = mx + logf(se);
    float mx2 = -1e30f;
    for (int i = 0; i < NB; i++) mx2 = fmaxf(mx2, g_sent[i * NB + t]);
    float se2 = 0.f;
    for (int i = 0; i < NB; i++) se2 += expf(g_sent[i * NB + t] - mx2);
    float lc = mx2 + logf(se2);
    __shared__ float r1[128], r2[128], r3[128];
    r1[t] = lr; r2[t] = lc; r3[t] = rs;
    __syncthreads();
    for (int s = 64; s > 0; s >>= 1) {
        if (t < s) { r1[t] += r1[t + s]; r2[t] += r2[t + s]; r3[t] += r3[t + s]; }
        __syncthreads();
    }
    if (t == 0) out[0] = r1[0] + r2[0] - 2.f * r3[0] / (float)NB;
}

// text_scores[m] = H2[m,:] . W3 + b3 ; one warp per row
__global__ __launch_bounds__(256) void k_text(const float* __restrict__ W3,
                                              const float* __restrict__ b3,
                                              float* __restrict__ out)
{
    const int warp = (blockIdx.x * 256 + threadIdx.x) >> 5;
    const int lane = threadIdx.x & 31;
    if (warp >= BPROWS) return;
    const float* row = g_H2 + (size_t)warp * HH;
    float s = 0.f;
    #pragma unroll
    for (int k = lane * 4; k < HH; k += 128) {
        float4 h = *(const float4*)(row + k);
        float4 w = *(const float4*)(W3 + k);
        s += h.x * w.x + h.y * w.y + h.z * w.z + h.w * w.w;
    }
    #pragma unroll
    for (int off = 16; off; off >>= 1) s += __shfl_xor_sync(0xffffffffu, s, off);
    if (lane == 0) out[1 + NB * NNL + warp] = s + b3[0];
}

// ---------------------------------------------------------------
extern "C" void kernel_launch(void* const* d_in, const int* in_sizes, int n_in,
                              void* d_out, int out_size)
{
    const float* S   = (const float*)d_in[0];   // (128,32,512)
    const float* I   = (const float*)d_in[1];   // (128,36,1024)
    const float* sm  = (const float*)d_in[2];   // (128,32)
    const float* im  = (const float*)d_in[3];   // (128,36)
    const float* Wg  = (const float*)d_in[4];   // (512,1024)
    const float* W1  = (const float*)d_in[5];   // (1536,512)
    const float* b1  = (const float*)d_in[6];   // (512)
    const float* W2  = (const float*)d_in[7];   // (512,512)
    const float* b2  = (const float*)d_in[8];   // (512)
    const float* W3  = (const float*)d_in[9];   // (512,1)
    const float* b3  = (const float*)d_in[10];  // (1)
    float* out = (float*)d_out;

    k_init_pairs<<<1, 512>>>();

    // Image-grounding path
    k_gemm_G<<<dim3(DV / 128, BNROWS / 128), 256>>>(S, Wg);
    k_M<<<NB, 256>>>(I, out);
    k_A<<<NB, 64>>>(sm, im);
    k_sent<<<NB, NB>>>(im);
    k_loss<<<1, NB>>>(out);

    // Text path: U = S@W1[0:512], V = S@W1[512:1024], then product GEMM + GEMM2
    k_gemm_U<<<dim3(HH / 128, BNROWS / 128), 256>>>(S, W1);
    k_gemm_V<<<dim3(HH / 128, BNROWS / 128), 256>>>(S, W1 + (size_t)DS * HH);
    k_prodgemm<<<dim3(HH / 128, BPROWS / 128), 256>>>(S, W1 + (size_t)2 * DS * HH, b1);
    k_gemm_H2<<<dim3(HH / 128, BPROWS / 128), 256>>>(W2, b2);
    k_text<<<BPROWS / 8, 256>>>(W3, b3, out);
}

// round 7
// speedup vs baseline: 1.6258x; 1.6258x over previous
#include <cuda_runtime.h>
#include <cuda_bf16.h>
#include <cstdint>
#include <stdint.h>
#include <math.h>

// Problem constants
#define NB 128
#define NN 32
#define NLW 36
#define DS 512
#define DV 1024
#define HH 512
#define NP 496
#define NNL (NN*NLW)      // 1152
#define BNROWS (NB*NN)    // 4096
#define BPROWS (NB*NP)    // 63488
#define KAUG 1536          // 3*512 augmented K
#define NCH 48             // KAUG / 32

// ---- scratch (__device__ globals; no runtime allocation) ----
__device__ __nv_bfloat16 g_Ball[(size_t)2048 * KAUG];   // [Wg^T;W1a^T;W1b^T] aug (hi|hi|lo)
__device__ __nv_bfloat16 g_W1ct[(size_t)HH * KAUG];     // W1c^T aug
__device__ __nv_bfloat16 g_W2t [(size_t)HH * KAUG];     // W2^T aug
__device__ __nv_bfloat16 g_H1hi[(size_t)BPROWS * HH];   // H1 hi
__device__ __nv_bfloat16 g_H1lo[(size_t)BPROWS * HH];   // H1 lo
__device__ float g_GUV[(size_t)BNROWS * 2048];          // [G | U | V] fp32
__device__ float g_tpart[(size_t)2 * BPROWS];
__device__ float g_M[NB * NNL];
__device__ float g_Avec[NB * NLW];
__device__ float g_cs[NB];
__device__ float g_ci[NB];
__device__ float g_Msum[NB];
__device__ float g_sent[NB * NB];
__device__ int   g_iu[NP];
__device__ int   g_ju[NP];

// =============================================================
// helpers
// =============================================================
__device__ __forceinline__ uint32_t s2u(const void* p) {
    uint32_t a;
    asm("{ .reg .u64 t; cvta.to.shared.u64 t, %1; cvt.u32.u64 %0, t; }" : "=r"(a) : "l"(p));
    return a;
}
__device__ __forceinline__ void ldsm_x4(uint32_t* r, uint32_t addr) {
    asm volatile("ldmatrix.sync.aligned.m8n8.x4.shared.b16 {%0,%1,%2,%3}, [%4];"
        : "=r"(r[0]), "=r"(r[1]), "=r"(r[2]), "=r"(r[3]) : "r"(addr));
}
__device__ __forceinline__ void mma16816(float* c, const uint32_t* a, uint32_t b0, uint32_t b1) {
    asm volatile(
        "mma.sync.aligned.m16n8k16.row.col.f32.bf16.bf16.f32 "
        "{%0,%1,%2,%3}, {%4,%5,%6,%7}, {%8,%9}, {%0,%1,%2,%3};"
        : "+f"(c[0]), "+f"(c[1]), "+f"(c[2]), "+f"(c[3])
        : "r"(a[0]), "r"(a[1]), "r"(a[2]), "r"(a[3]), "r"(b0), "r"(b1));
}
#define CPASYNC16(dst, src) asm volatile("cp.async.cg.shared.global [%0], [%1], 16;" :: "r"(dst), "l"(src))
#define CPCOMMIT()          asm volatile("cp.async.commit_group;" ::: "memory")
#define CPWAIT1()           asm volatile("cp.async.wait_group 1;" ::: "memory")
#define CPWAIT0()           asm volatile("cp.async.wait_group 0;" ::: "memory")

__device__ __forceinline__ void split2(float v, __nv_bfloat16& h, __nv_bfloat16& l) {
    h = __float2bfloat16(v);
    l = __float2bfloat16(v - __bfloat162float(h));
}
__device__ __forceinline__ uint32_t pack_pair(float a, float b, int take_lo) {
    __nv_bfloat16 ha, la, hb, lb;
    split2(a, ha, la); split2(b, hb, lb);
    __nv_bfloat162 r = take_lo ? __halves2bfloat162(la, lb) : __halves2bfloat162(ha, hb);
    return *(uint32_t*)&r;
}

// =============================================================
// Prep kernels
// =============================================================
__global__ void k_init_pairs() {
    int p = threadIdx.x;
    if (p >= NP) return;
    int cum = 0;
    for (int i = 0; i < NN; i++) {
        int cnt = NN - 1 - i;
        if (p < cum + cnt) { g_iu[p] = i; g_ju[p] = i + 1 + (p - cum); return; }
        cum += cnt;
    }
}
// B aug layout per row: cols [0,512)=hi, [512,1024)=hi, [1024,1536)=lo
__device__ __forceinline__ void store_b_aug(__nv_bfloat16* row, int c, float v) {
    __nv_bfloat16 h, l; split2(v, h, l);
    row[c] = h; row[512 + c] = h; row[1024 + c] = l;
}
__global__ void k_prep_Ball(const float* __restrict__ Wg, const float* __restrict__ W1) {
    int n = blockIdx.x;                 // 2048
    int c0 = threadIdx.x * 4;           // 128 thr
    __nv_bfloat16* row = g_Ball + (size_t)n * KAUG;
    #pragma unroll
    for (int t = 0; t < 4; t++) {
        int c = c0 + t;
        float w;
        if (n < 1024)      w = Wg[(size_t)c * DV + n];
        else if (n < 1536) w = W1[(size_t)c * HH + (n - 1024)];
        else               w = W1[(size_t)(512 + c) * HH + (n - 1536)];
        store_b_aug(row, c, w);
    }
}
__global__ void k_prep_W1ct(const float* __restrict__ W1) {
    int n = blockIdx.x;
    int c0 = threadIdx.x * 4;
    __nv_bfloat16* row = g_W1ct + (size_t)n * KAUG;
    #pragma unroll
    for (int t = 0; t < 4; t++) {
        int c = c0 + t;
        store_b_aug(row, c, W1[(size_t)(1024 + c) * HH + n]);
    }
}
__global__ void k_prep_W2t(const float* __restrict__ W2) {
    int n = blockIdx.x;
    int c0 = threadIdx.x * 4;
    __nv_bfloat16* row = g_W2t + (size_t)n * KAUG;
    #pragma unroll
    for (int t = 0; t < 4; t++) {
        int c = c0 + t;
        store_b_aug(row, c, W2[(size_t)c * HH + n]);
    }
}

// =============================================================
// HMMA GEMM: BM=128, BN=256, BK=32, 512 threads (16 warps, 4x4),
// warp tile 32x64 (2 m16 x 8 n8). A generated on the fly (split fp32->bf16),
// B pre-augmented bf16 via cp.async. Double-buffered SMEM.
// EPI 0: A from S rows (GEMM0), C -> g_GUV fp32 (ld 2048)
// EPI 1: A = S_i ⊙ S_j  (GEMM1), epi: +U+V+b1, relu, -> g_H1hi/g_H1lo
// EPI 2: A from g_H1hi/lo (GEMM2), epi: relu(+b2)·W3 row-reduce -> g_tpart
// =============================================================
#define AOFF(s) ((s) * 10240u)
#define BOFF(s) (20480u + (s) * 20480u)
#define SPART   61440u
#define SMEM_TOT 61952
#define ARS 40   // A/B smem row stride in bf16 elems (80B)

template<int EPI>
__global__ __launch_bounds__(512, 1)
void k_gemm_mma(const float* __restrict__ S,
                const float* __restrict__ bias,
                const float* __restrict__ W3)
{
    extern __shared__ char smem[];
    const uint32_t sb = s2u(smem);
    const int tid = threadIdx.x;
    const int m0 = blockIdx.y * 128;
    const int n0 = blockIdx.x * 256;

    const __nv_bfloat16* __restrict__ Bg =
        (EPI == 0) ? g_Ball : (EPI == 1) ? g_W1ct : g_W2t;

    // ---- A loader setup: thread t -> row rA = t>>2, k-chunk (t&3)*8
    const int rA  = tid >> 2;
    const int kcA = (tid & 3) * 8;
    const int rowA = m0 + rA;
    const float* pA0 = nullptr;
    const float* pA1 = nullptr;
    size_t rowAoff = 0;
    if (EPI == 0) {
        pA0 = S + (size_t)rowA * DS;
    } else if (EPI == 1) {
        int b_ = rowA / NP, p_ = rowA - b_ * NP;
        pA0 = S + (size_t)(b_ * NN + g_iu[p_]) * DS;
        pA1 = S + (size_t)(b_ * NN + g_ju[p_]) * DS;
    } else {
        rowAoff = (size_t)rowA * HH;
    }
    const uint32_t aDstOff = (uint32_t)(rA * (ARS * 2) + kcA * 2);

    // ---- fill lambdas
    auto fillA = [&](int s, int ch) {
        int augk = ch * 32;
        int blk = augk >> 9;
        int kk = (augk & 511) + kcA;
        if (EPI == 2) {
            const __nv_bfloat16* src = (blk == 1) ? g_H1lo : g_H1hi;
            uint4 v = *(const uint4*)(src + rowAoff + kk);
            *(uint4*)(smem + AOFF(s) + aDstOff) = v;
        } else {
            float4 x0 = *(const float4*)(pA0 + kk);
            float4 x1 = *(const float4*)(pA0 + kk + 4);
            float f0 = x0.x, f1 = x0.y, f2 = x0.z, f3 = x0.w;
            float f4 = x1.x, f5 = x1.y, f6 = x1.z, f7 = x1.w;
            if (EPI == 1) {
                float4 y0 = *(const float4*)(pA1 + kk);
                float4 y1 = *(const float4*)(pA1 + kk + 4);
                f0 *= y0.x; f1 *= y0.y; f2 *= y0.z; f3 *= y0.w;
                f4 *= y1.x; f5 *= y1.y; f6 *= y1.z; f7 *= y1.w;
            }
            uint4 v;
            v.x = pack_pair(f0, f1, blk == 1);
            v.y = pack_pair(f2, f3, blk == 1);
            v.z = pack_pair(f4, f5, blk == 1);
            v.w = pack_pair(f6, f7, blk == 1);
            *(uint4*)(smem + AOFF(s) + aDstOff) = v;
        }
    };
    auto fillB = [&](int s, int ch) {
        int augk = ch * 32;
        #pragma unroll
        for (int rep = 0; rep < 2; rep++) {
            int gg = tid + rep * 512;
            int rb = gg >> 2, cb = (gg & 3) * 8;
            uint32_t dst = sb + BOFF(s) + (uint32_t)(rb * (ARS * 2) + cb * 2);
            const __nv_bfloat16* src = Bg + (size_t)(n0 + rb) * KAUG + augk + cb;
            CPASYNC16(dst, src);
        }
        CPCOMMIT();
    };

    // ---- warp layout
    const int wid = tid >> 5;
    const int wm = wid >> 2;     // 0..3  (rows: wm*32)
    const int wn = wid & 3;      // 0..3  (cols: wn*64)
    const int l = tid & 31;

    float acc[2][8][4];
    #pragma unroll
    for (int mi = 0; mi < 2; mi++)
        #pragma unroll
        for (int nb = 0; nb < 8; nb++)
            #pragma unroll
            for (int q = 0; q < 4; q++) acc[mi][nb][q] = 0.f;

    if (EPI == 2) {
        if (tid < 128) *(float*)(smem + SPART + tid * 4) = 0.f;
    }

    // ldmatrix intra-tile offsets (bytes)
    const uint32_t lrow = (uint32_t)(l & 15);
    const uint32_t lcol8 = (uint32_t)((l >> 4) * 8);

    fillA(0, 0); fillB(0, 0);
    for (int ch = 0; ch < NCH; ch++) {
        const int s = ch & 1;
        if (ch + 1 < NCH) { fillA(s ^ 1, ch + 1); fillB(s ^ 1, ch + 1); CPWAIT1(); }
        else              { CPWAIT0(); }
        __syncthreads();

        const uint32_t abase = sb + AOFF(s);
        const uint32_t bbase = sb + BOFF(s);
        #pragma unroll
        for (int ks = 0; ks < 2; ks++) {
            uint32_t afr[2][4];
            #pragma unroll
            for (int mi = 0; mi < 2; mi++) {
                uint32_t addr = abase + ((uint32_t)(wm * 32 + mi * 16) + lrow) * (ARS * 2)
                              + ((uint32_t)(ks * 16) + lcol8) * 2;
                ldsm_x4(afr[mi], addr);
            }
            uint32_t bfr[4][4];
            #pragma unroll
            for (int np = 0; np < 4; np++) {
                uint32_t addr = bbase + ((uint32_t)(wn * 64 + np * 16) + lrow) * (ARS * 2)
                              + ((uint32_t)(ks * 16) + lcol8) * 2;
                ldsm_x4(bfr[np], addr);
            }
            #pragma unroll
            for (int mi = 0; mi < 2; mi++)
                #pragma unroll
                for (int nb = 0; nb < 8; nb++) {
                    int np = nb >> 1, hf = nb & 1;
                    mma16816(acc[mi][nb], afr[mi], bfr[np][hf], bfr[np][2 + hf]);
                }
        }
        __syncthreads();
    }

    // ---- epilogue (register accumulators) ----
    float rsum[2][2] = {{0.f, 0.f}, {0.f, 0.f}};
    #pragma unroll
    for (int mi = 0; mi < 2; mi++) {
        const int rl = wm * 32 + mi * 16 + (l >> 2);
        const int row0 = m0 + rl;
        const int row1 = row0 + 8;
        const float *U0 = nullptr, *V0 = nullptr, *U1 = nullptr, *V1 = nullptr;
        if (EPI == 1) {
            int b0_ = row0 / NP, p0_ = row0 - b0_ * NP;
            int b1_ = row1 / NP, p1_ = row1 - b1_ * NP;
            U0 = g_GUV + (size_t)(b0_ * NN + g_iu[p0_]) * 2048 + 1024;
            V0 = g_GUV + (size_t)(b0_ * NN + g_ju[p0_]) * 2048 + 1536;
            U1 = g_GUV + (size_t)(b1_ * NN + g_iu[p1_]) * 2048 + 1024;
            V1 = g_GUV + (size_t)(b1_ * NN + g_ju[p1_]) * 2048 + 1536;
        }
        #pragma unroll
        for (int nb = 0; nb < 8; nb++) {
            const int col = n0 + wn * 64 + nb * 8 + (l & 3) * 2;
            float c0 = acc[mi][nb][0], c1 = acc[mi][nb][1];
            float c2 = acc[mi][nb][2], c3 = acc[mi][nb][3];
            if (EPI == 0) {
                float2 u = {c0, c1}, v = {c2, c3};
                *(float2*)&g_GUV[(size_t)row0 * 2048 + col] = u;
                *(float2*)&g_GUV[(size_t)row1 * 2048 + col] = v;
            } else if (EPI == 1) {
                float v0 = fmaxf(c0 + U0[col]     + V0[col]     + bias[col],     0.f);
                float v1 = fmaxf(c1 + U0[col + 1] + V0[col + 1] + bias[col + 1], 0.f);
                float v2 = fmaxf(c2 + U1[col]     + V1[col]     + bias[col],     0.f);
                float v3 = fmaxf(c3 + U1[col + 1] + V1[col + 1] + bias[col + 1], 0.f);
                __nv_bfloat16 h0, l0, h1, l1, h2, l2, h3, l3;
                split2(v0, h0, l0); split2(v1, h1, l1);
                split2(v2, h2, l2); split2(v3, h3, l3);
                *(__nv_bfloat162*)&g_H1hi[(size_t)row0 * HH + col] = __halves2bfloat162(h0, h1);
                *(__nv_bfloat162*)&g_H1lo[(size_t)row0 * HH + col] = __halves2bfloat162(l0, l1);
                *(__nv_bfloat162*)&g_H1hi[(size_t)row1 * HH + col] = __halves2bfloat162(h2, h3);
                *(__nv_bfloat162*)&g_H1lo[(size_t)row1 * HH + col] = __halves2bfloat162(l2, l3);
            } else {
                float w0 = W3[col], w1 = W3[col + 1];
                float bb0 = bias[col], bb1 = bias[col + 1];
                rsum[mi][0] += fmaxf(c0 + bb0, 0.f) * w0 + fmaxf(c1 + bb1, 0.f) * w1;
                rsum[mi][1] += fmaxf(c2 + bb0, 0.f) * w0 + fmaxf(c3 + bb1, 0.f) * w1;
            }
        }
    }
    if (EPI == 2) {
        __syncthreads();   // spart zeroed before loop; ensure visible (also loop syncs cover)
        #pragma unroll
        for (int mi = 0; mi < 2; mi++) {
            #pragma unroll
            for (int q = 0; q < 2; q++) {
                float v = rsum[mi][q];
                v += __shfl_xor_sync(0xffffffffu, v, 1);
                v += __shfl_xor_sync(0xffffffffu, v, 2);
                if ((l & 3) == 0) {
                    int rl = wm * 32 + mi * 16 + (l >> 2) + q * 8;
                    atomicAdd((float*)(smem + SPART + rl * 4), v);
                }
            }
        }
        __syncthreads();
        if (tid < 128)
            g_tpart[(size_t)blockIdx.x * BPROWS + m0 + tid] = *(float*)(smem + SPART + tid * 4);
    }
}

// =============================================================
// Post-GEMM small kernels
// =============================================================
__global__ __launch_bounds__(256) void k_M(const float* __restrict__ I,
                                           float* __restrict__ out)
{
    __shared__ float Gs[32][65];
    __shared__ float Is[40][65];
    const int b = blockIdx.x;
    const int tid = threadIdx.x;
    const int n = tid >> 3;
    const int lg = tid & 7;
    float acc[5] = {0.f, 0.f, 0.f, 0.f, 0.f};

    for (int kt = 0; kt < DV; kt += 64) {
        __syncthreads();
        for (int t = tid; t < 32 * 64; t += 256) {
            int r = t >> 6, c = t & 63;
            Gs[r][c] = g_GUV[(size_t)(b * NN + r) * 2048 + kt + c];
        }
        for (int t = tid; t < 40 * 64; t += 256) {
            int r = t >> 6, c = t & 63;
            Is[r][c] = (r < NLW) ? I[(size_t)b * NLW * DV + (size_t)r * DV + kt + c] : 0.f;
        }
        __syncthreads();
        #pragma unroll 4
        for (int c = 0; c < 64; c++) {
            float g = Gs[n][c];
            #pragma unroll
            for (int s = 0; s < 5; s++)
                acc[s] = fmaf(g, Is[lg + 8 * s][c], acc[s]);
        }
    }
    #pragma unroll
    for (int s = 0; s < 5; s++) {
        int l = lg + 8 * s;
        if (l < NLW) {
            float v = acc[s];
            g_M[b * NNL + n * NLW + l] = v;
            out[1 + b * NNL + n * NLW + l] = v;
        }
    }
}

__global__ void k_A(const float* __restrict__ sm, const float* __restrict__ im)
{
    const int b = blockIdx.x, t = threadIdx.x;
    __shared__ float red[64];
    __shared__ float sms[32];
    if (t < 32) sms[t] = sm[b * NN + t];
    __syncthreads();
    float msum = 0.f;
    for (int o = t; o < NNL; o += 64) msum += g_M[b * NNL + o];
    red[t] = msum;
    if (t < NLW) {
        float a = 0.f;
        #pragma unroll
        for (int n = 0; n < NN; n++)
            a = fmaf(g_M[b * NNL + n * NLW + t], sms[n], a);
        g_Avec[b * NLW + t] = a;
    }
    __syncthreads();
    for (int s = 32; s > 0; s >>= 1) {
        if (t < s) red[t] += red[t + s];
        __syncthreads();
    }
    if (t == 0) {
        g_Msum[b] = red[0];
        float cs = 0.f, ci = 0.f;
        for (int n = 0; n < NN; n++) cs += sms[n];
        for (int l = 0; l < NLW; l++) ci += im[b * NLW + l];
        g_cs[b] = cs;
        g_ci[b] = ci;
    }
}

__global__ void k_sent(const float* __restrict__ im)
{
    const int i = blockIdx.x, j = threadIdx.x;
    __shared__ float As[NLW];
    __shared__ float csI, msI;
    if (j < NLW) As[j] = g_Avec[i * NLW + j];
    if (j == 0) { csI = g_cs[i]; msI = g_Msum[i]; }
    __syncthreads();
    float d = 0.f;
    #pragma unroll
    for (int l = 0; l < NLW; l++) d = fmaf(As[l], im[j * NLW + l], d);
    float cnt = csI * g_ci[j];
    g_sent[i * NB + j] = (cnt > 0.f) ? (d / cnt) : (msI / (float)NNL);
}

__global__ void k_loss(float* __restrict__ out)
{
    const int t = threadIdx.x;
    float mx = -1e30f;
    for (int j = 0; j < NB; j++) mx = fmaxf(mx, g_sent[t * NB + j]);
    float se = 0.f, rs = 0.f;
    for (int j = 0; j < NB; j++) {
        float v = g_sent[t * NB + j];
        se += expf(v - mx);
        rs += v;
    }
    float lr = mx + logf(se);
    float mx2 = -1e30f;
    for (int i = 0; i < NB; i++) mx2 = fmaxf(mx2, g_sent[i * NB + t]);
    float se2 = 0.f;
    for (int i = 0; i < NB; i++) se2 += expf(g_sent[i * NB + t] - mx2);
    float lc = mx2 + logf(se2);
    __shared__ float r1[128], r2[128], r3[128];
    r1[t] = lr; r2[t] = lc; r3[t] = rs;
    __syncthreads();
    for (int s = 64; s > 0; s >>= 1) {
        if (t < s) { r1[t] += r1[t + s]; r2[t] += r2[t + s]; r3[t] += r3[t + s]; }
        __syncthreads();
    }
    if (t == 0) out[0] = r1[0] + r2[0] - 2.f * r3[0] / (float)NB;
}

__global__ void k_text_final(const float* __restrict__ b3, float* __restrict__ out)
{
    int m = blockIdx.x * 256 + threadIdx.x;
    if (m >= BPROWS) return;
    out[1 + NB * NNL + m] = b3[0] + g_tpart[m] + g_tpart[(size_t)BPROWS + m];
}

// =============================================================
extern "C" void kernel_launch(void* const* d_in, const int* in_sizes, int n_in,
                              void* d_out, int out_size)
{
    const float* S   = (const float*)d_in[0];
    const float* I   = (const float*)d_in[1];
    const float* sm  = (const float*)d_in[2];
    const float* im  = (const float*)d_in[3];
    const float* Wg  = (const float*)d_in[4];
    const float* W1  = (const float*)d_in[5];
    const float* b1  = (const float*)d_in[6];
    const float* W2  = (const float*)d_in[7];
    const float* b2  = (const float*)d_in[8];
    const float* W3  = (const float*)d_in[9];
    const float* b3  = (const float*)d_in[10];
    float* out = (float*)d_out;

    cudaFuncSetAttribute(k_gemm_mma<0>, cudaFuncAttributeMaxDynamicSharedMemorySize, SMEM_TOT);
    cudaFuncSetAttribute(k_gemm_mma<1>, cudaFuncAttributeMaxDynamicSharedMemorySize, SMEM_TOT);
    cudaFuncSetAttribute(k_gemm_mma<2>, cudaFuncAttributeMaxDynamicSharedMemorySize, SMEM_TOT);

    // preps
    k_init_pairs<<<1, 512>>>();
    k_prep_Ball<<<2048, 128>>>(Wg, W1);
    k_prep_W1ct<<<512, 128>>>(W1);
    k_prep_W2t<<<512, 128>>>(W2);

    // GEMM0: [G|U|V] = S @ [Wg | W1a | W1b]   (M=4096, N=2048)
    k_gemm_mma<0><<<dim3(2048 / 256, BNROWS / 128), 512, SMEM_TOT>>>(S, nullptr, nullptr);

    // image-grounding tail
    k_M<<<NB, 256>>>(I, out);
    k_A<<<NB, 64>>>(sm, im);
    k_sent<<<NB, NB>>>(im);
    k_loss<<<1, NB>>>(out);

    // text path
    k_gemm_mma<1><<<dim3(HH / 256, BPROWS / 128), 512, SMEM_TOT>>>(S, b1, nullptr);
    k_gemm_mma<2><<<dim3(HH / 256, BPROWS / 128), 512, SMEM_TOT>>>(nullptr, b2, W3);
    k_text_final<<<(BPROWS + 255) / 256, 256>>>(b3, out);
}

// round 8
// speedup vs baseline: 1.8913x; 1.1633x over previous
#include <cuda_runtime.h>
#include <cuda_bf16.h>
#include <cstdint>
#include <stdint.h>
#include <math.h>

// Problem constants
#define NB 128
#define NN 32
#define NLW 36
#define DS 512
#define DV 1024
#define HH 512
#define NP 496
#define NNL (NN*NLW)      // 1152
#define BNROWS (NB*NN)    // 4096
#define BPROWS (NB*NP)    // 63488
#define KAUG 1536          // 3*512 augmented K
#define NCH 24             // KAUG / 64  (BK=64)

// ---- scratch (__device__ globals; no runtime allocation) ----
__device__ __nv_bfloat16 g_Ball[(size_t)2048 * KAUG];   // [Wg^T;W1a^T;W1b^T] aug (hi|hi|lo)
__device__ __nv_bfloat16 g_W1ct[(size_t)HH * KAUG];     // W1c^T aug
__device__ __nv_bfloat16 g_W2t [(size_t)HH * KAUG];     // W2^T aug
__device__ __nv_bfloat16 g_H1hi[(size_t)BPROWS * HH];   // H1 hi
__device__ __nv_bfloat16 g_H1lo[(size_t)BPROWS * HH];   // H1 lo
__device__ float g_GUV[(size_t)BNROWS * 2048];          // [G | U | V] fp32
__device__ float g_tpart[(size_t)2 * BPROWS];
__device__ float g_M[NB * NNL];
__device__ float g_Avec[NB * NLW];
__device__ float g_cs[NB];
__device__ float g_ci[NB];
__device__ float g_Msum[NB];
__device__ float g_sent[NB * NB];
__device__ int   g_iu[NP];
__device__ int   g_ju[NP];

// =============================================================
// helpers
// =============================================================
__device__ __forceinline__ uint32_t s2u(const void* p) {
    uint32_t a;
    asm("{ .reg .u64 t; cvta.to.shared.u64 t, %1; cvt.u32.u64 %0, t; }" : "=r"(a) : "l"(p));
    return a;
}
__device__ __forceinline__ void ldsm_x4(uint32_t* r, uint32_t addr) {
    asm volatile("ldmatrix.sync.aligned.m8n8.x4.shared.b16 {%0,%1,%2,%3}, [%4];"
        : "=r"(r[0]), "=r"(r[1]), "=r"(r[2]), "=r"(r[3]) : "r"(addr));
}
__device__ __forceinline__ void mma16816(float* c, const uint32_t* a, uint32_t b0, uint32_t b1) {
    asm volatile(
        "mma.sync.aligned.m16n8k16.row.col.f32.bf16.bf16.f32 "
        "{%0,%1,%2,%3}, {%4,%5,%6,%7}, {%8,%9}, {%0,%1,%2,%3};"
        : "+f"(c[0]), "+f"(c[1]), "+f"(c[2]), "+f"(c[3])
        : "r"(a[0]), "r"(a[1]), "r"(a[2]), "r"(a[3]), "r"(b0), "r"(b1));
}
#define CPASYNC16(dst, src) asm volatile("cp.async.cg.shared.global [%0], [%1], 16;" :: "r"(dst), "l"(src))
#define CPCOMMIT()          asm volatile("cp.async.commit_group;" ::: "memory")
#define CPWAIT1()           asm volatile("cp.async.wait_group 1;" ::: "memory")
#define CPWAIT0()           asm volatile("cp.async.wait_group 0;" ::: "memory")

__device__ __forceinline__ void split2(float v, __nv_bfloat16& h, __nv_bfloat16& l) {
    h = __float2bfloat16(v);
    l = __float2bfloat16(v - __bfloat162float(h));
}
__device__ __forceinline__ uint32_t pack_pair(float a, float b, int take_lo) {
    __nv_bfloat16 ha, la, hb, lb;
    split2(a, ha, la); split2(b, hb, lb);
    __nv_bfloat162 r = take_lo ? __halves2bfloat162(la, lb) : __halves2bfloat162(ha, hb);
    return *(uint32_t*)&r;
}

// =============================================================
// Prep kernels
// =============================================================
__global__ void k_init_pairs() {
    int p = threadIdx.x;
    if (p >= NP) return;
    int cum = 0;
    for (int i = 0; i < NN; i++) {
        int cnt = NN - 1 - i;
        if (p < cum + cnt) { g_iu[p] = i; g_ju[p] = i + 1 + (p - cum); return; }
        cum += cnt;
    }
}
// B aug layout per row: cols [0,512)=hi, [512,1024)=hi, [1024,1536)=lo
__device__ __forceinline__ void store_b_aug(__nv_bfloat16* row, int c, float v) {
    __nv_bfloat16 h, l; split2(v, h, l);
    row[c] = h; row[512 + c] = h; row[1024 + c] = l;
}
__global__ void k_prep_Ball(const float* __restrict__ Wg, const float* __restrict__ W1) {
    int n = blockIdx.x;                 // 2048
    int c0 = threadIdx.x * 4;           // 128 thr
    __nv_bfloat16* row = g_Ball + (size_t)n * KAUG;
    #pragma unroll
    for (int t = 0; t < 4; t++) {
        int c = c0 + t;
        float w;
        if (n < 1024)      w = Wg[(size_t)c * DV + n];
        else if (n < 1536) w = W1[(size_t)c * HH + (n - 1024)];
        else               w = W1[(size_t)(512 + c) * HH + (n - 1536)];
        store_b_aug(row, c, w);
    }
}
__global__ void k_prep_W1ct(const float* __restrict__ W1) {
    int n = blockIdx.x;
    int c0 = threadIdx.x * 4;
    __nv_bfloat16* row = g_W1ct + (size_t)n * KAUG;
    #pragma unroll
    for (int t = 0; t < 4; t++) {
        int c = c0 + t;
        store_b_aug(row, c, W1[(size_t)(1024 + c) * HH + n]);
    }
}
__global__ void k_prep_W2t(const float* __restrict__ W2) {
    int n = blockIdx.x;
    int c0 = threadIdx.x * 4;
    __nv_bfloat16* row = g_W2t + (size_t)n * KAUG;
    #pragma unroll
    for (int t = 0; t < 4; t++) {
        int c = c0 + t;
        store_b_aug(row, c, W2[(size_t)c * HH + n]);
    }
}

// =============================================================
// HMMA GEMM: BM=128, BN=256, BK=64, 512 threads (16 warps, 4x4),
// warp tile 32x64. A generated on the fly (split fp32->bf16),
// B pre-augmented bf16 via cp.async. Double-buffered SMEM.
// EPI 0: A from S rows (GEMM0), C -> g_GUV fp32 (ld 2048)
// EPI 1: A = S_i ⊙ S_j  (GEMM1), epi: +U+V+b1, relu, -> g_H1hi/g_H1lo
// EPI 2: A from g_H1hi/lo (GEMM2), epi: relu(+b2)·W3 row-reduce -> g_tpart
// =============================================================
#define ARS 72                       // smem row stride in bf16 (144 B)
#define ABYTES (128 * ARS * 2)       // 18432
#define BBYTES (256 * ARS * 2)       // 36864
#define AOFF(s) ((uint32_t)((s) * ABYTES))
#define BOFF(s) ((uint32_t)(2 * ABYTES + (s) * BBYTES))
#define SPART   ((uint32_t)(2 * ABYTES + 2 * BBYTES))   // 110592
#define SMEM_TOT (2 * ABYTES + 2 * BBYTES + 512)        // 111104

template<int EPI>
__global__ __launch_bounds__(512, 1)
void k_gemm_mma(const float* __restrict__ S,
                const float* __restrict__ bias,
                const float* __restrict__ W3)
{
    extern __shared__ char smem[];
    const uint32_t sb = s2u(smem);
    const int tid = threadIdx.x;
    const int m0 = blockIdx.y * 128;
    const int n0 = blockIdx.x * 256;

    const __nv_bfloat16* __restrict__ Bg =
        (EPI == 0) ? g_Ball : (EPI == 1) ? g_W1ct : g_W2t;

    // ---- A loader: thread t -> rows rA0 = t>>3 and rA0+64, k-cols (t&7)*8..+7
    const int rA0 = tid >> 3;
    const int rA1 = rA0 + 64;
    const int kcA = (tid & 7) * 8;
    const float *p0a = nullptr, *p0b = nullptr, *p1a = nullptr, *p1b = nullptr;
    size_t rowOff0 = 0, rowOff1 = 0;
    {
        const int row0 = m0 + rA0, row1 = m0 + rA1;
        if (EPI == 0) {
            p0a = S + (size_t)row0 * DS;
            p1a = S + (size_t)row1 * DS;
        } else if (EPI == 1) {
            int b0_ = row0 / NP, q0 = row0 - b0_ * NP;
            int b1_ = row1 / NP, q1 = row1 - b1_ * NP;
            p0a = S + (size_t)(b0_ * NN + g_iu[q0]) * DS;
            p0b = S + (size_t)(b0_ * NN + g_ju[q0]) * DS;
            p1a = S + (size_t)(b1_ * NN + g_iu[q1]) * DS;
            p1b = S + (size_t)(b1_ * NN + g_ju[q1]) * DS;
        } else {
            rowOff0 = (size_t)row0 * HH;
            rowOff1 = (size_t)row1 * HH;
        }
    }
    const uint32_t aDst0 = (uint32_t)(rA0 * (ARS * 2) + kcA * 2);
    const uint32_t aDst1 = (uint32_t)(rA1 * (ARS * 2) + kcA * 2);

    auto fillA = [&](int s, int ch) {
        const int blk = ch >> 3;                    // 0:hi 1:lo 2:hi
        const int kk = ((ch & 7) << 6) + kcA;       // col within 512-block
        if (EPI == 2) {
            const __nv_bfloat16* src = (blk == 1) ? g_H1lo : g_H1hi;
            *(uint4*)(smem + AOFF(s) + aDst0) = *(const uint4*)(src + rowOff0 + kk);
            *(uint4*)(smem + AOFF(s) + aDst1) = *(const uint4*)(src + rowOff1 + kk);
        } else {
            const int lo = (blk == 1);
            float4 x0 = *(const float4*)(p0a + kk);
            float4 x1 = *(const float4*)(p0a + kk + 4);
            float f0 = x0.x, f1 = x0.y, f2 = x0.z, f3 = x0.w;
            float f4 = x1.x, f5 = x1.y, f6 = x1.z, f7 = x1.w;
            if (EPI == 1) {
                float4 y0 = *(const float4*)(p0b + kk);
                float4 y1 = *(const float4*)(p0b + kk + 4);
                f0 *= y0.x; f1 *= y0.y; f2 *= y0.z; f3 *= y0.w;
                f4 *= y1.x; f5 *= y1.y; f6 *= y1.z; f7 *= y1.w;
            }
            uint4 v;
            v.x = pack_pair(f0, f1, lo); v.y = pack_pair(f2, f3, lo);
            v.z = pack_pair(f4, f5, lo); v.w = pack_pair(f6, f7, lo);
            *(uint4*)(smem + AOFF(s) + aDst0) = v;

            float4 z0 = *(const float4*)(p1a + kk);
            float4 z1 = *(const float4*)(p1a + kk + 4);
            float g0 = z0.x, g1 = z0.y, g2 = z0.z, g3 = z0.w;
            float g4 = z1.x, g5 = z1.y, g6 = z1.z, g7 = z1.w;
            if (EPI == 1) {
                float4 w0 = *(const float4*)(p1b + kk);
                float4 w1 = *(const float4*)(p1b + kk + 4);
                g0 *= w0.x; g1 *= w0.y; g2 *= w0.z; g3 *= w0.w;
                g4 *= w1.x; g5 *= w1.y; g6 *= w1.z; g7 *= w1.w;
            }
            uint4 u;
            u.x = pack_pair(g0, g1, lo); u.y = pack_pair(g2, g3, lo);
            u.z = pack_pair(g4, g5, lo); u.w = pack_pair(g6, g7, lo);
            *(uint4*)(smem + AOFF(s) + aDst1) = u;
        }
    };
    auto fillB = [&](int s, int ch) {
        const int augk = ch * 64;
        #pragma unroll
        for (int rep = 0; rep < 4; rep++) {
            int gg = tid + rep * 512;
            int rb = gg >> 3, cb = (gg & 7) * 8;
            uint32_t dst = sb + BOFF(s) + (uint32_t)(rb * (ARS * 2) + cb * 2);
            const __nv_bfloat16* src = Bg + (size_t)(n0 + rb) * KAUG + augk + cb;
            CPASYNC16(dst, src);
        }
        CPCOMMIT();
    };

    // ---- warp layout
    const int wid = tid >> 5;
    const int wm = wid >> 2;     // rows: wm*32
    const int wn = wid & 3;      // cols: wn*64
    const int l = tid & 31;

    float acc[2][8][4];
    #pragma unroll
    for (int mi = 0; mi < 2; mi++)
        #pragma unroll
        for (int nb = 0; nb < 8; nb++)
            #pragma unroll
            for (int q = 0; q < 4; q++) acc[mi][nb][q] = 0.f;

    if (EPI == 2) {
        if (tid < 128) *(float*)(smem + SPART + tid * 4) = 0.f;
    }

    const uint32_t lrow = (uint32_t)(l & 15);
    const uint32_t lcol8 = (uint32_t)((l >> 4) * 8);

    fillA(0, 0); fillB(0, 0);
    for (int ch = 0; ch < NCH; ch++) {
        const int s = ch & 1;
        if (ch + 1 < NCH) { fillA(s ^ 1, ch + 1); fillB(s ^ 1, ch + 1); CPWAIT1(); }
        else              { CPWAIT0(); }
        __syncthreads();

        const uint32_t abase = sb + AOFF(s);
        const uint32_t bbase = sb + BOFF(s);
        #pragma unroll
        for (int ks = 0; ks < 4; ks++) {
            uint32_t afr[2][4];
            #pragma unroll
            for (int mi = 0; mi < 2; mi++) {
                uint32_t addr = abase + ((uint32_t)(wm * 32 + mi * 16) + lrow) * (ARS * 2)
                              + ((uint32_t)(ks * 16) + lcol8) * 2;
                ldsm_x4(afr[mi], addr);
            }
            uint32_t bfr[4][4];
            #pragma unroll
            for (int np = 0; np < 4; np++) {
                uint32_t addr = bbase + ((uint32_t)(wn * 64 + np * 16) + lrow) * (ARS * 2)
                              + ((uint32_t)(ks * 16) + lcol8) * 2;
                ldsm_x4(bfr[np], addr);
            }
            #pragma unroll
            for (int mi = 0; mi < 2; mi++)
                #pragma unroll
                for (int nb = 0; nb < 8; nb++) {
                    int np = nb >> 1, hf = nb & 1;
                    mma16816(acc[mi][nb], afr[mi], bfr[np][hf], bfr[np][2 + hf]);
                }
        }
        __syncthreads();
    }

    // ---- epilogue (register accumulators) ----
    float rsum[2][2] = {{0.f, 0.f}, {0.f, 0.f}};
    #pragma unroll
    for (int mi = 0; mi < 2; mi++) {
        const int rl = wm * 32 + mi * 16 + (l >> 2);
        const int row0 = m0 + rl;
        const int row1 = row0 + 8;
        const float *U0 = nullptr, *V0 = nullptr, *U1 = nullptr, *V1 = nullptr;
        if (EPI == 1) {
            int b0_ = row0 / NP, p0_ = row0 - b0_ * NP;
            int b1_ = row1 / NP, p1_ = row1 - b1_ * NP;
            U0 = g_GUV + (size_t)(b0_ * NN + g_iu[p0_]) * 2048 + 1024;
            V0 = g_GUV + (size_t)(b0_ * NN + g_ju[p0_]) * 2048 + 1536;
            U1 = g_GUV + (size_t)(b1_ * NN + g_iu[p1_]) * 2048 + 1024;
            V1 = g_GUV + (size_t)(b1_ * NN + g_ju[p1_]) * 2048 + 1536;
        }
        #pragma unroll
        for (int nb = 0; nb < 8; nb++) {
            const int col = n0 + wn * 64 + nb * 8 + (l & 3) * 2;
            float c0 = acc[mi][nb][0], c1 = acc[mi][nb][1];
            float c2 = acc[mi][nb][2], c3 = acc[mi][nb][3];
            if (EPI == 0) {
                float2 u = {c0, c1}, v = {c2, c3};
                *(float2*)&g_GUV[(size_t)row0 * 2048 + col] = u;
                *(float2*)&g_GUV[(size_t)row1 * 2048 + col] = v;
            } else if (EPI == 1) {
                float v0 = fmaxf(c0 + U0[col]     + V0[col]     + bias[col],     0.f);
                float v1 = fmaxf(c1 + U0[col + 1] + V0[col + 1] + bias[col + 1], 0.f);
                float v2 = fmaxf(c2 + U1[col]     + V1[col]     + bias[col],     0.f);
                float v3 = fmaxf(c3 + U1[col + 1] + V1[col + 1] + bias[col + 1], 0.f);
                __nv_bfloat16 h0, l0, h1, l1, h2, l2, h3, l3;
                split2(v0, h0, l0); split2(v1, h1, l1);
                split2(v2, h2, l2); split2(v3, h3, l3);
                *(__nv_bfloat162*)&g_H1hi[(size_t)row0 * HH + col] = __halves2bfloat162(h0, h1);
                *(__nv_bfloat162*)&g_H1lo[(size_t)row0 * HH + col] = __halves2bfloat162(l0, l1);
                *(__nv_bfloat162*)&g_H1hi[(size_t)row1 * HH + col] = __halves2bfloat162(h2, h3);
                *(__nv_bfloat162*)&g_H1lo[(size_t)row1 * HH + col] = __halves2bfloat162(l2, l3);
            } else {
                float w0 = W3[col], w1 = W3[col + 1];
                float bb0 = bias[col], bb1 = bias[col + 1];
                rsum[mi][0] += fmaxf(c0 + bb0, 0.f) * w0 + fmaxf(c1 + bb1, 0.f) * w1;
                rsum[mi][1] += fmaxf(c2 + bb0, 0.f) * w0 + fmaxf(c3 + bb1, 0.f) * w1;
            }
        }
    }
    if (EPI == 2) {
        __syncthreads();
        #pragma unroll
        for (int mi = 0; mi < 2; mi++) {
            #pragma unroll
            for (int q = 0; q < 2; q++) {
                float v = rsum[mi][q];
                v += __shfl_xor_sync(0xffffffffu, v, 1);
                v += __shfl_xor_sync(0xffffffffu, v, 2);
                if ((l & 3) == 0) {
                    int rl = wm * 32 + mi * 16 + (l >> 2) + q * 8;
                    atomicAdd((float*)(smem + SPART + rl * 4), v);
                }
            }
        }
        __syncthreads();
        if (tid < 128)
            g_tpart[(size_t)blockIdx.x * BPROWS + m0 + tid] = *(float*)(smem + SPART + tid * 4);
    }
}

// =============================================================
// Post-GEMM small kernels
// =============================================================
__global__ __launch_bounds__(256) void k_M(const float* __restrict__ I,
                                           float* __restrict__ out)
{
    __shared__ float Gs[32][65];
    __shared__ float Is[40][65];
    const int b = blockIdx.x;
    const int tid = threadIdx.x;
    const int n = tid >> 3;
    const int lg = tid & 7;
    float acc[5] = {0.f, 0.f, 0.f, 0.f, 0.f};

    for (int kt = 0; kt < DV; kt += 64) {
        __syncthreads();
        for (int t = tid; t < 32 * 64; t += 256) {
            int r = t >> 6, c = t & 63;
            Gs[r][c] = g_GUV[(size_t)(b * NN + r) * 2048 + kt + c];
        }
        for (int t = tid; t < 40 * 64; t += 256) {
            int r = t >> 6, c = t & 63;
            Is[r][c] = (r < NLW) ? I[(size_t)b * NLW * DV + (size_t)r * DV + kt + c] : 0.f;
        }
        __syncthreads();
        #pragma unroll 4
        for (int c = 0; c < 64; c++) {
            float g = Gs[n][c];
            #pragma unroll
            for (int s = 0; s < 5; s++)
                acc[s] = fmaf(g, Is[lg + 8 * s][c], acc[s]);
        }
    }
    #pragma unroll
    for (int s = 0; s < 5; s++) {
        int l = lg + 8 * s;
        if (l < NLW) {
            float v = acc[s];
            g_M[b * NNL + n * NLW + l] = v;
            out[1 + b * NNL + n * NLW + l] = v;
        }
    }
}

__global__ void k_A(const float* __restrict__ sm, const float* __restrict__ im)
{
    const int b = blockIdx.x, t = threadIdx.x;
    __shared__ float red[64];
    __shared__ float sms[32];
    if (t < 32) sms[t] = sm[b * NN + t];
    __syncthreads();
    float msum = 0.f;
    for (int o = t; o < NNL; o += 64) msum += g_M[b * NNL + o];
    red[t] = msum;
    if (t < NLW) {
        float a = 0.f;
        #pragma unroll
        for (int n = 0; n < NN; n++)
            a = fmaf(g_M[b * NNL + n * NLW + t], sms[n], a);
        g_Avec[b * NLW + t] = a;
    }
    __syncthreads();
    for (int s = 32; s > 0; s >>= 1) {
        if (t < s) red[t] += red[t + s];
        __syncthreads();
    }
    if (t == 0) {
        g_Msum[b] = red[0];
        float cs = 0.f, ci = 0.f;
        for (int n = 0; n < NN; n++) cs += sms[n];
        for (int l = 0; l < NLW; l++) ci += im[b * NLW + l];
        g_cs[b] = cs;
        g_ci[b] = ci;
    }
}

__global__ void k_sent(const float* __restrict__ im)
{
    const int i = blockIdx.x, j = threadIdx.x;
    __shared__ float As[NLW];
    __shared__ float csI, msI;
    if (j < NLW) As[j] = g_Avec[i * NLW + j];
    if (j == 0) { csI = g_cs[i]; msI = g_Msum[i]; }
    __syncthreads();
    float d = 0.f;
    #pragma unroll
    for (int l = 0; l < NLW; l++) d = fmaf(As[l], im[j * NLW + l], d);
    float cnt = csI * g_ci[j];
    g_sent[i * NB + j] = (cnt > 0.f) ? (d / cnt) : (msI / (float)NNL);
}

__global__ void k_loss(float* __restrict__ out)
{
    const int t = threadIdx.x;
    float mx = -1e30f;
    for (int j = 0; j < NB; j++) mx = fmaxf(mx, g_sent[t * NB + j]);
    float se = 0.f, rs = 0.f;
    for (int j = 0; j < NB; j++) {
        float v = g_sent[t * NB + j];
        se += expf(v - mx);
        rs += v;
    }
    float lr = mx + logf(se);
    float mx2 = -1e30f;
    for (int i = 0; i < NB; i++) mx2 = fmaxf(mx2, g_sent[i * NB + t]);
    float se2 = 0.f;
    for (int i = 0; i < NB; i++) se2 += expf(g_sent[i * NB + t] - mx2);
    float lc = mx2 + logf(se2);
    __shared__ float r1[128], r2[128], r3[128];
    r1[t] = lr; r2[t] = lc; r3[t] = rs;
    __syncthreads();
    for (int s = 64; s > 0; s >>= 1) {
        if (t < s) { r1[t] += r1[t + s]; r2[t] += r2[t + s]; r3[t] += r3[t + s]; }
        __syncthreads();
    }
    if (t == 0) out[0] = r1[0] + r2[0] - 2.f * r3[0] / (float)NB;
}

__global__ void k_text_final(const float* __restrict__ b3, float* __restrict__ out)
{
    int m = blockIdx.x * 256 + threadIdx.x;
    if (m >= BPROWS) return;
    out[1 + NB * NNL + m] = b3[0] + g_tpart[m] + g_tpart[(size_t)BPROWS + m];
}

// =============================================================
extern "C" void kernel_launch(void* const* d_in, const int* in_sizes, int n_in,
                              void* d_out, int out_size)
{
    const float* S   = (const float*)d_in[0];
    const float* I   = (const float*)d_in[1];
    const float* sm  = (const float*)d_in[2];
    const float* im  = (const float*)d_in[3];
    const float* Wg  = (const float*)d_in[4];
    const float* W1  = (const float*)d_in[5];
    const float* b1  = (const float*)d_in[6];
    const float* W2  = (const float*)d_in[7];
    const float* b2  = (const float*)d_in[8];
    const float* W3  = (const float*)d_in[9];
    const float* b3  = (const float*)d_in[10];
    float* out = (float*)d_out;

    cudaFuncSetAttribute(k_gemm_mma<0>, cudaFuncAttributeMaxDynamicSharedMemorySize, SMEM_TOT);
    cudaFuncSetAttribute(k_gemm_mma<1>, cudaFuncAttributeMaxDynamicSharedMemorySize, SMEM_TOT);
    cudaFuncSetAttribute(k_gemm_mma<2>, cudaFuncAttributeMaxDynamicSharedMemorySize, SMEM_TOT);

    // preps
    k_init_pairs<<<1, 512>>>();
    k_prep_Ball<<<2048, 128>>>(Wg, W1);
    k_prep_W1ct<<<512, 128>>>(W1);
    k_prep_W2t<<<512, 128>>>(W2);

    // GEMM0: [G|U|V] = S @ [Wg | W1a | W1b]   (M=4096, N=2048)
    k_gemm_mma<0><<<dim3(2048 / 256, BNROWS / 128), 512, SMEM_TOT>>>(S, nullptr, nullptr);

    // image-grounding tail
    k_M<<<NB, 256>>>(I, out);
    k_A<<<NB, 64>>>(sm, im);
    k_sent<<<NB, NB>>>(im);
    k_loss<<<1, NB>>>(out);

    // text path
    k_gemm_mma<1><<<dim3(HH / 256, BPROWS / 128), 512, SMEM_TOT>>>(S, b1, nullptr);
    k_gemm_mma<2><<<dim3(HH / 256, BPROWS / 128), 512, SMEM_TOT>>>(nullptr, b2, W3);
    k_text_final<<<(BPROWS + 255) / 256, 256>>>(b3, out);
}